// round 12
// baseline (speedup 1.0000x reference)
#include <cuda_runtime.h>
#include <cuda_bf16.h>
#include <math.h>
#include <stdint.h>

#define BATCH 2
#define LSEQ 2048
#define NTOK (BATCH*LSEQ)
#define INPUT_DIM 512
#define DMODEL 1024
#define NHEAD 16
#define HD 64
#define MLPH 4096
#define LN_EPS 1e-5f

// fp32 scratch
__device__ float g_h [NTOK*DMODEL];
__device__ float g_hn[NTOK*DMODEL];
// bf16 split activations
__device__ __nv_bfloat16 g_x_hi[NTOK*INPUT_DIM], g_x_lo[NTOK*INPUT_DIM];
__device__ __nv_bfloat16 g_hn_hi[NTOK*DMODEL],   g_hn_lo[NTOK*DMODEL];
__device__ __nv_bfloat16 g_kq_hi[NTOK*2*DMODEL], g_kq_lo[NTOK*2*DMODEL];
__device__ __nv_bfloat16 g_v_hi[NTOK*DMODEL],    g_v_lo[NTOK*DMODEL];
__device__ __nv_bfloat16 g_o_hi[NTOK*DMODEL],    g_o_lo[NTOK*DMODEL];
__device__ __nv_bfloat16 g_xo_hi[NTOK*DMODEL],   g_xo_lo[NTOK*DMODEL];
__device__ __nv_bfloat16 g_ml_hi[NTOK*MLPH],     g_ml_lo[NTOK*MLPH];
// bf16 split transposed weights [N][K]
__device__ __nv_bfloat16 g_wte_hi[DMODEL*INPUT_DIM], g_wte_lo[DMODEL*INPUT_DIM];
__device__ __nv_bfloat16 g_kqw_hi[2*DMODEL*DMODEL],  g_kqw_lo[2*DMODEL*DMODEL];
__device__ __nv_bfloat16 g_vw_hi[DMODEL*DMODEL],     g_vw_lo[DMODEL*DMODEL];
__device__ __nv_bfloat16 g_aow_hi[DMODEL*DMODEL],    g_aow_lo[DMODEL*DMODEL];
__device__ __nv_bfloat16 g_fcw_hi[MLPH*DMODEL],      g_fcw_lo[MLPH*DMODEL];
__device__ __nv_bfloat16 g_pjw_hi[INPUT_DIM*MLPH],   g_pjw_lo[INPUT_DIM*MLPH];

__device__ __forceinline__ void split2(float v, __nv_bfloat16& hi, __nv_bfloat16& lo) {
    hi = __float2bfloat16(v);
    lo = __float2bfloat16(v - __bfloat162float(hi));
}
__device__ __forceinline__ uint32_t pack2(__nv_bfloat16 a, __nv_bfloat16 b) {
    __nv_bfloat162 t = __halves2bfloat162(a, b);
    return *reinterpret_cast<uint32_t*>(&t);
}
__device__ __forceinline__ uint32_t smem_u32(const void* p) {
    return (uint32_t)__cvta_generic_to_shared(p);
}
__device__ __forceinline__ void cpasync16(uint32_t dst, const void* src) {
    asm volatile("cp.async.cg.shared.global [%0], [%1], 16;" :: "r"(dst), "l"(src));
}
__device__ __forceinline__ void ldm_x4(uint32_t* r, uint32_t a) {
    asm volatile("ldmatrix.sync.aligned.m8n8.x4.shared.b16 {%0,%1,%2,%3}, [%4];"
                 : "=r"(r[0]), "=r"(r[1]), "=r"(r[2]), "=r"(r[3]) : "r"(a));
}
__device__ __forceinline__ void ldm_x4t(uint32_t* r, uint32_t a) {
    asm volatile("ldmatrix.sync.aligned.m8n8.x4.trans.shared.b16 {%0,%1,%2,%3}, [%4];"
                 : "=r"(r[0]), "=r"(r[1]), "=r"(r[2]), "=r"(r[3]) : "r"(a));
}
__device__ __forceinline__ void mma_bf16(float* d, const uint32_t* a, const uint32_t* b) {
    asm volatile("mma.sync.aligned.m16n8k16.row.col.f32.bf16.bf16.f32 "
                 "{%0,%1,%2,%3}, {%4,%5,%6,%7}, {%8,%9}, {%0,%1,%2,%3};"
                 : "+f"(d[0]), "+f"(d[1]), "+f"(d[2]), "+f"(d[3])
                 : "r"(a[0]), "r"(a[1]), "r"(a[2]), "r"(a[3]), "r"(b[0]), "r"(b[1]));
}

// ---- fused weight transpose + split (all 6 weights, one launch) ----
struct WEnt { const float* W; __nv_bfloat16* hi; __nv_bfloat16* lo; int K; int N; int start; };
struct WTable { WEnt e[6]; int total; };

__global__ void wsplit_all(WTable t)
{
    __shared__ float tile[32][33];
    const int bid = blockIdx.x;
    const float* W = nullptr; __nv_bfloat16 *hi = nullptr, *lo = nullptr;
    int K = 0, N = 0, local = 0;
#pragma unroll
    for (int i = 0; i < 6; i++) {
        const int next = (i + 1 < 6) ? t.e[i + 1].start : t.total;
        if (bid >= t.e[i].start && bid < next) {
            W = t.e[i].W; hi = t.e[i].hi; lo = t.e[i].lo;
            K = t.e[i].K; N = t.e[i].N; local = bid - t.e[i].start;
        }
    }
    const int nb = N >> 5;
    const int n0 = (local % nb) * 32, k0 = (local / nb) * 32;
    const int tx = threadIdx.x, ty = threadIdx.y;
#pragma unroll
    for (int i = 0; i < 32; i += 8)
        tile[ty + i][tx] = W[(size_t)(k0 + ty + i) * N + n0 + tx];
    __syncthreads();
#pragma unroll
    for (int i = 0; i < 32; i += 8) {
        __nv_bfloat16 h_, l_;
        split2(tile[tx][ty + i], h_, l_);
        size_t o = (size_t)(n0 + ty + i) * K + k0 + tx;
        hi[o] = h_; lo[o] = l_;
    }
}

__global__ __launch_bounds__(256)
void xsplit_kernel(const float* __restrict__ x, __nv_bfloat16* __restrict__ hi,
                   __nv_bfloat16* __restrict__ lo, int n)
{
    int i = blockIdx.x * 256 + threadIdx.x;
    if (i < n) { __nv_bfloat16 h_, l_; split2(x[i], h_, l_); hi[i] = h_; lo[i] = l_; }
}

// ---- HMMA GEMM: split-3 bf16, CTA tile 128x128x32, 4 warps x (64x64) ----
enum { EP_EMBED = 0, EP_BIAS = 1, EP_RES = 2, EP_GELU = 3, EP_SPLIT = 4 };
#define HM_SMEM (2*32768)

template <int EPI>
__global__ __launch_bounds__(128)
void hmma_gemm(int M, int N, int K,
               const __nv_bfloat16* __restrict__ Ahi, const __nv_bfloat16* __restrict__ Alo,
               const __nv_bfloat16* __restrict__ Bhi, const __nv_bfloat16* __restrict__ Blo,
               const float* __restrict__ bias, const float* __restrict__ extra,
               float* __restrict__ Cf,
               __nv_bfloat16* __restrict__ Chi, __nv_bfloat16* __restrict__ Clo)
{
    extern __shared__ char dsm[];
    const uint32_t sbase = smem_u32(dsm);
    const int tid = threadIdx.x, wid = tid >> 5, lane = tid & 31;
    const int m0 = blockIdx.y * 128, n0 = blockIdx.x * 128;
    const int wm = (wid & 1) * 64, wn = (wid >> 1) * 64;

    float acc[4][8][4];
#pragma unroll
    for (int i = 0; i < 4; i++)
#pragma unroll
        for (int j = 0; j < 8; j++)
#pragma unroll
            for (int q = 0; q < 4; q++) acc[i][j][q] = 0.f;

    uint32_t a_off[4], a_sw[4];
    const uint32_t a_half = lane >> 4;
#pragma unroll
    for (int i = 0; i < 4; i++) {
        int row = wm + i * 16 + (lane & 7) + ((lane >> 3) & 1) * 8;
        a_off[i] = row * 64;
        a_sw[i]  = (row >> 1) & 3;
    }
    // paired-x4 B fragment addressing: matrix group g = lane>>3,
    // j offset = lane>>4, k-half = (lane>>3)&1
    uint32_t bp_off[4], bp_sw[4];
    const uint32_t b_half = (lane >> 3) & 1;
#pragma unroll
    for (int jp = 0; jp < 4; jp++) {
        int row = wn + (jp * 2 + (lane >> 4)) * 8 + (lane & 7);
        bp_off[jp] = row * 64;
        bp_sw[jp]  = (row >> 1) & 3;
    }

    const int nch = K >> 5;
    auto stage = [&](int i) {
        const uint32_t buf = sbase + (i & 1) * 32768;
        const int kofs = i << 5;
#pragma unroll
        for (int t = 0; t < 4; t++) {
            const __nv_bfloat16* src = (t == 0) ? Ahi : (t == 1) ? Alo : (t == 2) ? Bhi : Blo;
            const int rb = (t < 2) ? m0 : n0;
            const uint32_t db = buf + t * 8192;
#pragma unroll
            for (int u = 0; u < 4; u++) {
                int idx = u * 128 + tid;
                int row = idx >> 2, c = idx & 3;
                cpasync16(db + row * 64 + ((c ^ ((row >> 1) & 3)) << 4),
                          src + (size_t)(rb + row) * K + kofs + c * 8);
            }
        }
    };

    stage(0);
    asm volatile("cp.async.commit_group;" ::: "memory");

    for (int i = 0; i < nch; i++) {
        if (i + 1 < nch) {
            stage(i + 1);
            asm volatile("cp.async.commit_group;" ::: "memory");
            asm volatile("cp.async.wait_group 1;" ::: "memory");
        } else {
            asm volatile("cp.async.wait_group 0;" ::: "memory");
        }
        __syncthreads();

        const uint32_t buf = sbase + (i & 1) * 32768;
#pragma unroll
        for (int p = 0; p < 3; p++) {
            const uint32_t ab = buf + (p == 1 ? 8192 : 0);
            const uint32_t bb = buf + (p == 2 ? 24576 : 16384);
#pragma unroll
            for (int kk = 0; kk < 2; kk++) {
                uint32_t af[4][4], bf[8][2];
#pragma unroll
                for (int t = 0; t < 4; t++)
                    ldm_x4(af[t], ab + a_off[t] + (((kk * 2 + a_half) ^ a_sw[t]) << 4));
#pragma unroll
                for (int jp = 0; jp < 4; jp++)
                    ldm_x4(&bf[jp * 2][0], bb + bp_off[jp] + (((kk * 2 + b_half) ^ bp_sw[jp]) << 4));
#pragma unroll
                for (int ti = 0; ti < 4; ti++)
#pragma unroll
                    for (int tj = 0; tj < 8; tj++)
                        mma_bf16(acc[ti][tj], af[ti], bf[tj]);
            }
        }
        __syncthreads();
    }

#pragma unroll
    for (int i = 0; i < 4; i++) {
#pragma unroll
        for (int half = 0; half < 2; half++) {
            const int row = m0 + wm + i * 16 + (lane >> 2) + half * 8;
#pragma unroll
            for (int j = 0; j < 8; j++) {
                const int col = n0 + wn + j * 8 + (lane & 3) * 2;
                float2 bv = *reinterpret_cast<const float2*>(bias + col);
                float v0 = acc[i][j][half * 2 + 0] + bv.x;
                float v1 = acc[i][j][half * 2 + 1] + bv.y;
                if (EPI == EP_EMBED || EPI == EP_RES) {
                    const int er = (EPI == EP_EMBED) ? (row & (LSEQ - 1)) : row;
                    float2 ev = *reinterpret_cast<const float2*>(extra + (size_t)er * N + col);
                    v0 += ev.x; v1 += ev.y;
                }
                if (EPI == EP_GELU) {
                    v0 = 0.5f * v0 * (1.f + erff(v0 * 0.70710678118654752f));
                    v1 = 0.5f * v1 * (1.f + erff(v1 * 0.70710678118654752f));
                }
                if (EPI == EP_GELU || EPI == EP_SPLIT) {
                    __nv_bfloat16 h0, l0, h1, l1;
                    split2(v0, h0, l0); split2(v1, h1, l1);
                    *reinterpret_cast<uint32_t*>(Chi + (size_t)row * N + col) = pack2(h0, h1);
                    *reinterpret_cast<uint32_t*>(Clo + (size_t)row * N + col) = pack2(l0, l1);
                } else {
                    *reinterpret_cast<float2*>(Cf + (size_t)row * N + col) = make_float2(v0, v1);
                }
            }
        }
    }
}

// ---- LayerNorm ----
template <bool WF32, bool WSPLIT>
__global__ __launch_bounds__(256)
void ln_kernel(const float* __restrict__ x, const float* __restrict__ w,
               const float* __restrict__ b, float* __restrict__ y,
               __nv_bfloat16* __restrict__ yhi, __nv_bfloat16* __restrict__ ylo)
{
    const int row = blockIdx.x, c = threadIdx.x * 4;
    float4 v = *reinterpret_cast<const float4*>(x + (size_t)row * DMODEL + c);
    float s = v.x + v.y + v.z + v.w;
    float sq = v.x*v.x + v.y*v.y + v.z*v.z + v.w*v.w;
#pragma unroll
    for (int o = 16; o; o >>= 1) {
        s += __shfl_xor_sync(~0u, s, o); sq += __shfl_xor_sync(~0u, sq, o);
    }
    __shared__ float ss[8], ssq[8];
    const int warp = threadIdx.x >> 5, lane = threadIdx.x & 31;
    if (lane == 0) { ss[warp] = s; ssq[warp] = sq; }
    __syncthreads();
    float tot = 0.f, totq = 0.f;
#pragma unroll
    for (int i = 0; i < 8; i++) { tot += ss[i]; totq += ssq[i]; }
    const float mu = tot / DMODEL, var = totq / DMODEL - mu * mu;
    const float inv = rsqrtf(var + LN_EPS);
    float4 wv = *reinterpret_cast<const float4*>(w + c);
    float4 bv = *reinterpret_cast<const float4*>(b + c);
    float4 o;
    o.x = (v.x-mu)*inv*wv.x + bv.x; o.y = (v.y-mu)*inv*wv.y + bv.y;
    o.z = (v.z-mu)*inv*wv.z + bv.z; o.w = (v.w-mu)*inv*wv.w + bv.w;
    if (WF32) *reinterpret_cast<float4*>(y + (size_t)row * DMODEL + c) = o;
    if (WSPLIT) {
        __nv_bfloat16 h0,l0,h1,l1,h2,l2,h3,l3;
        split2(o.x,h0,l0); split2(o.y,h1,l1); split2(o.z,h2,l2); split2(o.w,h3,l3);
        *reinterpret_cast<uint2*>(yhi + (size_t)row*DMODEL + c) = make_uint2(pack2(h0,h1), pack2(h2,h3));
        *reinterpret_cast<uint2*>(ylo + (size_t)row*DMODEL + c) = make_uint2(pack2(l0,l1), pack2(l2,l3));
    }
}

// ---- HMMA flash attention (causal), split-3 bf16, 8 warps x 16 q-rows ----
#define FA_SMEM (32768 + 2*32768)

__global__ __launch_bounds__(256, 1)
void fa_kernel(const __nv_bfloat16* __restrict__ kqhi, const __nv_bfloat16* __restrict__ kqlo,
               const __nv_bfloat16* __restrict__ vhi,  const __nv_bfloat16* __restrict__ vlo,
               __nv_bfloat16* __restrict__ ohi, __nv_bfloat16* __restrict__ olo)
{
    extern __shared__ char dsm[];
    const uint32_t sb = smem_u32(dsm);
    const int tid = threadIdx.x, w = tid >> 5, lane = tid & 31;
    const int qt = blockIdx.x, bh = blockIdx.y;
    const int bidx = bh >> 4, h = bh & 15;
    const int rowbase = bidx * LSEQ;
    const int q0 = qt * 128;
    const int jmax = 2 * qt + 1;

#pragma unroll
    for (int t = 0; t < 8; t++) {
        const int arr = t >> 2;
        const int row = ((t & 3) * 256 + tid) >> 3;
        const int ch = tid & 7;
        const __nv_bfloat16* base = arr ? kqlo : kqhi;
        cpasync16(sb + arr * 16384 + row * 128 + ((ch ^ (row & 7)) << 4),
                  base + (size_t)(rowbase + q0 + row) * (2 * DMODEL) + DMODEL + h * HD + ch * 8);
    }
    auto stageKV = [&](int jt, int b) {
        const uint32_t buf = sb + 32768 + b * 32768;
        const int n0 = jt * 64;
#pragma unroll
        for (int t = 0; t < 8; t++) {
            const int arr = t >> 1;
            const int row = ((t & 1) * 256 + tid) >> 3;
            const int ch = tid & 7;
            const __nv_bfloat16* base = (arr == 0) ? kqhi : (arr == 1) ? kqlo
                                      : (arr == 2) ? vhi : vlo;
            const size_t stride = (arr < 2) ? (2 * DMODEL) : DMODEL;
            cpasync16(buf + arr * 8192 + row * 128 + ((ch ^ (row & 7)) << 4),
                      base + (size_t)(rowbase + n0 + row) * stride + h * HD + ch * 8);
        }
    };
    stageKV(0, 0);
    asm volatile("cp.async.commit_group;" ::: "memory");

    const int r0 = q0 + w * 16 + (lane >> 2);
    float m0 = -INFINITY, m1 = -INFINITY, l0 = 0.f, l1 = 0.f;
    float o[8][4];
#pragma unroll
    for (int j = 0; j < 8; j++)
#pragma unroll
        for (int c = 0; c < 4; c++) o[j][c] = 0.f;

    uint32_t qh[4][4], ql[4][4];
    const int qrow = w * 16 + (lane & 7) + ((lane >> 3) & 1) * 8;
    const uint32_t qhalf = lane >> 4;
    // paired-x4 K fragment addressing
    const int kprow_base = (lane >> 4) * 8 + (lane & 7);   // + jp*16
    const uint32_t khalf4 = (lane >> 3) & 1;
    // paired-x4 V (trans) fragment addressing
    const int vrow4_base = ((lane >> 3) & 1) * 8 + (lane & 7);  // + kc*16
    const int vjofs = lane >> 4;                                 // + j2p*2

    for (int jt = 0; jt <= jmax; jt++) {
        if (jt < jmax) {
            stageKV(jt + 1, (jt + 1) & 1);
            asm volatile("cp.async.commit_group;" ::: "memory");
            asm volatile("cp.async.wait_group 1;" ::: "memory");
        } else {
            asm volatile("cp.async.wait_group 0;" ::: "memory");
        }
        __syncthreads();

        if (jt == 0) {
#pragma unroll
            for (int kc = 0; kc < 4; kc++) {
                const uint32_t co = (((kc * 2 + qhalf) ^ (qrow & 7)) << 4);
                ldm_x4(qh[kc], sb + qrow * 128 + co);
                ldm_x4(ql[kc], sb + 16384 + qrow * 128 + co);
            }
        }

        const uint32_t buf = sb + 32768 + (jt & 1) * 32768;
        const int n0 = jt * 64;

        float s[8][4];
#pragma unroll
        for (int j = 0; j < 8; j++)
#pragma unroll
            for (int c = 0; c < 4; c++) s[j][c] = 0.f;

#pragma unroll
        for (int jp = 0; jp < 4; jp++) {
            const int krow = jp * 16 + kprow_base;
            const uint32_t krsw = (uint32_t)(krow & 7);
#pragma unroll
            for (int kc = 0; kc < 4; kc++) {
                const uint32_t co = krow * 128 + (((kc * 2 + khalf4) ^ krsw) << 4);
                uint32_t kh4[4], kl4[4];
                ldm_x4(kh4, buf + co);
                ldm_x4(kl4, buf + 8192 + co);
                mma_bf16(s[jp*2+0], qh[kc], kh4 + 0);
                mma_bf16(s[jp*2+0], ql[kc], kh4 + 0);
                mma_bf16(s[jp*2+0], qh[kc], kl4 + 0);
                mma_bf16(s[jp*2+1], qh[kc], kh4 + 2);
                mma_bf16(s[jp*2+1], ql[kc], kh4 + 2);
                mma_bf16(s[jp*2+1], qh[kc], kl4 + 2);
            }
        }
#pragma unroll
        for (int j = 0; j < 8; j++) {
            s[j][0] *= 0.125f; s[j][1] *= 0.125f; s[j][2] *= 0.125f; s[j][3] *= 0.125f;
        }
        if (n0 + 63 > q0 + w * 16) {
#pragma unroll
            for (int j = 0; j < 8; j++) {
                const int c0 = n0 + j * 8 + (lane & 3) * 2;
                if (c0 > r0)     s[j][0] = -INFINITY;
                if (c0 + 1 > r0) s[j][1] = -INFINITY;
                if (c0 > r0 + 8)     s[j][2] = -INFINITY;
                if (c0 + 1 > r0 + 8) s[j][3] = -INFINITY;
            }
        }
        float mx0 = -INFINITY, mx1 = -INFINITY;
#pragma unroll
        for (int j = 0; j < 8; j++) {
            mx0 = fmaxf(mx0, fmaxf(s[j][0], s[j][1]));
            mx1 = fmaxf(mx1, fmaxf(s[j][2], s[j][3]));
        }
        mx0 = fmaxf(mx0, __shfl_xor_sync(~0u, mx0, 1));
        mx0 = fmaxf(mx0, __shfl_xor_sync(~0u, mx0, 2));
        mx1 = fmaxf(mx1, __shfl_xor_sync(~0u, mx1, 1));
        mx1 = fmaxf(mx1, __shfl_xor_sync(~0u, mx1, 2));
        const float nm0 = fmaxf(m0, mx0), nm1 = fmaxf(m1, mx1);
        const float cr0 = __expf(m0 - nm0), cr1 = __expf(m1 - nm1);
        float rs0 = 0.f, rs1 = 0.f;
#pragma unroll
        for (int j = 0; j < 8; j++) {
            s[j][0] = __expf(s[j][0] - nm0); rs0 += s[j][0];
            s[j][1] = __expf(s[j][1] - nm0); rs0 += s[j][1];
            s[j][2] = __expf(s[j][2] - nm1); rs1 += s[j][2];
            s[j][3] = __expf(s[j][3] - nm1); rs1 += s[j][3];
        }
        rs0 += __shfl_xor_sync(~0u, rs0, 1); rs0 += __shfl_xor_sync(~0u, rs0, 2);
        rs1 += __shfl_xor_sync(~0u, rs1, 1); rs1 += __shfl_xor_sync(~0u, rs1, 2);
        l0 = l0 * cr0 + rs0; l1 = l1 * cr1 + rs1;
        m0 = nm0; m1 = nm1;
#pragma unroll
        for (int j = 0; j < 8; j++) {
            o[j][0] *= cr0; o[j][1] *= cr0; o[j][2] *= cr1; o[j][3] *= cr1;
        }
        uint32_t ph[4][4], pl[4][4];
#pragma unroll
        for (int kc = 0; kc < 4; kc++) {
#pragma unroll
            for (int half = 0; half < 2; half++) {
                const int t2 = 2 * kc + half;
                __nv_bfloat16 a0, b0, a1, b1;
                split2(s[t2][0], a0, b0); split2(s[t2][1], a1, b1);
                ph[kc][half * 2 + 0] = pack2(a0, a1);
                pl[kc][half * 2 + 0] = pack2(b0, b1);
                split2(s[t2][2], a0, b0); split2(s[t2][3], a1, b1);
                ph[kc][half * 2 + 1] = pack2(a0, a1);
                pl[kc][half * 2 + 1] = pack2(b0, b1);
            }
        }
#pragma unroll
        for (int j2p = 0; j2p < 4; j2p++) {
#pragma unroll
            for (int kc = 0; kc < 4; kc++) {
                const int vrow = kc * 16 + vrow4_base;
                const int vj = j2p * 2 + vjofs;
                const uint32_t co = vrow * 128 + ((vj ^ (vrow & 7)) << 4);
                uint32_t vh4[4], vl4[4];
                ldm_x4t(vh4, buf + 16384 + co);
                ldm_x4t(vl4, buf + 24576 + co);
                mma_bf16(o[j2p*2+0], ph[kc], vh4 + 0);
                mma_bf16(o[j2p*2+0], pl[kc], vh4 + 0);
                mma_bf16(o[j2p*2+0], ph[kc], vl4 + 0);
                mma_bf16(o[j2p*2+1], ph[kc], vh4 + 2);
                mma_bf16(o[j2p*2+1], pl[kc], vh4 + 2);
                mma_bf16(o[j2p*2+1], ph[kc], vl4 + 2);
            }
        }
        __syncthreads();
    }

    const float il0 = 1.f / l0, il1 = 1.f / l1;
#pragma unroll
    for (int j2 = 0; j2 < 8; j2++) {
        const int col = h * HD + j2 * 8 + (lane & 3) * 2;
        float v0 = o[j2][0] * il0, v1 = o[j2][1] * il0;
        float v2 = o[j2][2] * il1, v3 = o[j2][3] * il1;
        __nv_bfloat16 h0, e0, h1, e1;
        split2(v0, h0, e0); split2(v1, h1, e1);
        *reinterpret_cast<uint32_t*>(ohi + (size_t)(rowbase + r0) * DMODEL + col) = pack2(h0, h1);
        *reinterpret_cast<uint32_t*>(olo + (size_t)(rowbase + r0) * DMODEL + col) = pack2(e0, e1);
        split2(v2, h0, e0); split2(v3, h1, e1);
        *reinterpret_cast<uint32_t*>(ohi + (size_t)(rowbase + r0 + 8) * DMODEL + col) = pack2(h0, h1);
        *reinterpret_cast<uint32_t*>(olo + (size_t)(rowbase + r0 + 8) * DMODEL + col) = pack2(e0, e1);
    }
}

extern "C" void kernel_launch(void* const* d_in, const int* in_sizes, int n_in,
                              void* d_out, int out_size)
{
    const float* x      = (const float*)d_in[0];
    const float* wte_w  = (const float*)d_in[1];
    const float* wte_b  = (const float*)d_in[2];
    const float* wpe    = (const float*)d_in[3];
    const float* ln1_w  = (const float*)d_in[4];
    const float* ln1_b  = (const float*)d_in[5];
    const float* kq_w   = (const float*)d_in[6];
    const float* kq_b   = (const float*)d_in[7];
    const float* v_w    = (const float*)d_in[8];
    const float* v_b    = (const float*)d_in[9];
    const float* ao_w   = (const float*)d_in[10];
    const float* ao_b   = (const float*)d_in[11];
    const float* ln2_w  = (const float*)d_in[12];
    const float* ln2_b  = (const float*)d_in[13];
    const float* fc_w   = (const float*)d_in[14];
    const float* fc_b   = (const float*)d_in[15];
    const float* proj_w = (const float*)d_in[16];
    const float* proj_b = (const float*)d_in[17];

    float *h, *hn;
    cudaGetSymbolAddress((void**)&h, g_h);
    cudaGetSymbolAddress((void**)&hn, g_hn);
    __nv_bfloat16 *xhi,*xlo,*hnhi,*hnlo,*kqhi,*kqlo,*vhi,*vlo,*ohi,*olo,*xohi,*xolo,*mlhi,*mllo;
    __nv_bfloat16 *wtehi,*wtelo,*kqwhi,*kqwlo,*vwhi,*vwlo,*aowhi,*aowlo,*fcwhi,*fcwlo,*pjwhi,*pjwlo;
    cudaGetSymbolAddress((void**)&xhi, g_x_hi);   cudaGetSymbolAddress((void**)&xlo, g_x_lo);
    cudaGetSymbolAddress((void**)&hnhi, g_hn_hi); cudaGetSymbolAddress((void**)&hnlo, g_hn_lo);
    cudaGetSymbolAddress((void**)&kqhi, g_kq_hi); cudaGetSymbolAddress((void**)&kqlo, g_kq_lo);
    cudaGetSymbolAddress((void**)&vhi, g_v_hi);   cudaGetSymbolAddress((void**)&vlo, g_v_lo);
    cudaGetSymbolAddress((void**)&ohi, g_o_hi);   cudaGetSymbolAddress((void**)&olo, g_o_lo);
    cudaGetSymbolAddress((void**)&xohi, g_xo_hi); cudaGetSymbolAddress((void**)&xolo, g_xo_lo);
    cudaGetSymbolAddress((void**)&mlhi, g_ml_hi); cudaGetSymbolAddress((void**)&mllo, g_ml_lo);
    cudaGetSymbolAddress((void**)&wtehi, g_wte_hi); cudaGetSymbolAddress((void**)&wtelo, g_wte_lo);
    cudaGetSymbolAddress((void**)&kqwhi, g_kqw_hi); cudaGetSymbolAddress((void**)&kqwlo, g_kqw_lo);
    cudaGetSymbolAddress((void**)&vwhi, g_vw_hi);   cudaGetSymbolAddress((void**)&vwlo, g_vw_lo);
    cudaGetSymbolAddress((void**)&aowhi, g_aow_hi); cudaGetSymbolAddress((void**)&aowlo, g_aow_lo);
    cudaGetSymbolAddress((void**)&fcwhi, g_fcw_hi); cudaGetSymbolAddress((void**)&fcwlo, g_fcw_lo);
    cudaGetSymbolAddress((void**)&pjwhi, g_pjw_hi); cudaGetSymbolAddress((void**)&pjwlo, g_pjw_lo);

    float* out0     = (float*)d_out;
    float* attn_out = out0 + (size_t)NTOK * INPUT_DIM;

    cudaFuncSetAttribute(hmma_gemm<EP_EMBED>, cudaFuncAttributeMaxDynamicSharedMemorySize, HM_SMEM);
    cudaFuncSetAttribute(hmma_gemm<EP_BIAS>,  cudaFuncAttributeMaxDynamicSharedMemorySize, HM_SMEM);
    cudaFuncSetAttribute(hmma_gemm<EP_RES>,   cudaFuncAttributeMaxDynamicSharedMemorySize, HM_SMEM);
    cudaFuncSetAttribute(hmma_gemm<EP_GELU>,  cudaFuncAttributeMaxDynamicSharedMemorySize, HM_SMEM);
    cudaFuncSetAttribute(hmma_gemm<EP_SPLIT>, cudaFuncAttributeMaxDynamicSharedMemorySize, HM_SMEM);
    cudaFuncSetAttribute(fa_kernel, cudaFuncAttributeMaxDynamicSharedMemorySize, FA_SMEM);

    // fused weight split table
    WTable wt;
    int cur = 0;
    auto set = [&](int i, const float* W, __nv_bfloat16* hi_, __nv_bfloat16* lo_, int K, int N) {
        wt.e[i].W = W; wt.e[i].hi = hi_; wt.e[i].lo = lo_;
        wt.e[i].K = K; wt.e[i].N = N; wt.e[i].start = cur;
        cur += (K / 32) * (N / 32);
    };
    set(0, wte_w,  wtehi, wtelo, INPUT_DIM, DMODEL);
    set(1, kq_w,   kqwhi, kqwlo, DMODEL, 2 * DMODEL);
    set(2, v_w,    vwhi,  vwlo,  DMODEL, DMODEL);
    set(3, ao_w,   aowhi, aowlo, DMODEL, DMODEL);
    set(4, fc_w,   fcwhi, fcwlo, DMODEL, MLPH);
    set(5, proj_w, pjwhi, pjwlo, MLPH, INPUT_DIM);
    wt.total = cur;

    dim3 wsb(32, 8);
    xsplit_kernel<<<(NTOK*INPUT_DIM)/256, 256>>>(x, xhi, xlo, NTOK*INPUT_DIM);
    wsplit_all<<<wt.total, wsb>>>(wt);

    hmma_gemm<EP_EMBED><<<dim3(DMODEL/128, NTOK/128), 128, HM_SMEM>>>(
        NTOK, DMODEL, INPUT_DIM, xhi, xlo, wtehi, wtelo, wte_b, wpe, h, nullptr, nullptr);
    ln_kernel<true, true><<<NTOK, 256>>>(h, ln1_w, ln1_b, hn, hnhi, hnlo);
    hmma_gemm<EP_SPLIT><<<dim3(2*DMODEL/128, NTOK/128), 128, HM_SMEM>>>(
        NTOK, 2*DMODEL, DMODEL, hnhi, hnlo, kqwhi, kqwlo, kq_b, nullptr, nullptr, kqhi, kqlo);
    hmma_gemm<EP_SPLIT><<<dim3(DMODEL/128, NTOK/128), 128, HM_SMEM>>>(
        NTOK, DMODEL, DMODEL, hnhi, hnlo, vwhi, vwlo, v_b, nullptr, nullptr, vhi, vlo);
    fa_kernel<<<dim3(LSEQ/128, BATCH*NHEAD), 256, FA_SMEM>>>(kqhi, kqlo, vhi, vlo, ohi, olo);
    hmma_gemm<EP_RES><<<dim3(DMODEL/128, NTOK/128), 128, HM_SMEM>>>(
        NTOK, DMODEL, DMODEL, ohi, olo, aowhi, aowlo, ao_b, hn, attn_out, nullptr, nullptr);
    ln_kernel<false, true><<<NTOK, 256>>>(attn_out, ln2_w, ln2_b, nullptr, xohi, xolo);
    hmma_gemm<EP_GELU><<<dim3(MLPH/128, NTOK/128), 128, HM_SMEM>>>(
        NTOK, MLPH, DMODEL, xohi, xolo, fcwhi, fcwlo, fc_b, nullptr, nullptr, mlhi, mllo);
    hmma_gemm<EP_BIAS><<<dim3(INPUT_DIM/128, NTOK/128), 128, HM_SMEM>>>(
        NTOK, INPUT_DIM, MLPH, mlhi, mllo, pjwhi, pjwlo, proj_b, nullptr, out0, nullptr, nullptr);
}

// round 14
// speedup vs baseline: 1.0081x; 1.0081x over previous
#include <cuda_runtime.h>
#include <cuda_bf16.h>
#include <math.h>
#include <stdint.h>

#define BATCH 2
#define LSEQ 2048
#define NTOK (BATCH*LSEQ)
#define INPUT_DIM 512
#define DMODEL 1024
#define NHEAD 16
#define HD 64
#define MLPH 4096
#define LN_EPS 1e-5f

// fp32 scratch
__device__ float g_h [NTOK*DMODEL];
__device__ float g_hn[NTOK*DMODEL];
// bf16 split activations
__device__ __nv_bfloat16 g_x_hi[NTOK*INPUT_DIM], g_x_lo[NTOK*INPUT_DIM];
__device__ __nv_bfloat16 g_hn_hi[NTOK*DMODEL],   g_hn_lo[NTOK*DMODEL];
__device__ __nv_bfloat16 g_kq_hi[NTOK*2*DMODEL], g_kq_lo[NTOK*2*DMODEL];
__device__ __nv_bfloat16 g_v_hi[NTOK*DMODEL],    g_v_lo[NTOK*DMODEL];
__device__ __nv_bfloat16 g_o_hi[NTOK*DMODEL],    g_o_lo[NTOK*DMODEL];
__device__ __nv_bfloat16 g_xo_hi[NTOK*DMODEL],   g_xo_lo[NTOK*DMODEL];
__device__ __nv_bfloat16 g_ml_hi[NTOK*MLPH],     g_ml_lo[NTOK*MLPH];
// bf16 split transposed weights [N][K]
__device__ __nv_bfloat16 g_wte_hi[DMODEL*INPUT_DIM], g_wte_lo[DMODEL*INPUT_DIM];
__device__ __nv_bfloat16 g_kqw_hi[2*DMODEL*DMODEL],  g_kqw_lo[2*DMODEL*DMODEL];
__device__ __nv_bfloat16 g_vw_hi[DMODEL*DMODEL],     g_vw_lo[DMODEL*DMODEL];
__device__ __nv_bfloat16 g_aow_hi[DMODEL*DMODEL],    g_aow_lo[DMODEL*DMODEL];
__device__ __nv_bfloat16 g_fcw_hi[MLPH*DMODEL],      g_fcw_lo[MLPH*DMODEL];
__device__ __nv_bfloat16 g_pjw_hi[INPUT_DIM*MLPH],   g_pjw_lo[INPUT_DIM*MLPH];

__device__ __forceinline__ void split2(float v, __nv_bfloat16& hi, __nv_bfloat16& lo) {
    hi = __float2bfloat16(v);
    lo = __float2bfloat16(v - __bfloat162float(hi));
}
__device__ __forceinline__ uint32_t pack2(__nv_bfloat16 a, __nv_bfloat16 b) {
    __nv_bfloat162 t = __halves2bfloat162(a, b);
    return *reinterpret_cast<uint32_t*>(&t);
}
__device__ __forceinline__ uint32_t smem_u32(const void* p) {
    return (uint32_t)__cvta_generic_to_shared(p);
}
__device__ __forceinline__ void cpasync16(uint32_t dst, const void* src) {
    asm volatile("cp.async.cg.shared.global [%0], [%1], 16;" :: "r"(dst), "l"(src));
}
__device__ __forceinline__ void ldm_x4(uint32_t* r, uint32_t a) {
    asm volatile("ldmatrix.sync.aligned.m8n8.x4.shared.b16 {%0,%1,%2,%3}, [%4];"
                 : "=r"(r[0]), "=r"(r[1]), "=r"(r[2]), "=r"(r[3]) : "r"(a));
}
__device__ __forceinline__ void ldm_x2(uint32_t* r, uint32_t a) {
    asm volatile("ldmatrix.sync.aligned.m8n8.x2.shared.b16 {%0,%1}, [%2];"
                 : "=r"(r[0]), "=r"(r[1]) : "r"(a));
}
__device__ __forceinline__ void ldm_x2t(uint32_t* r, uint32_t a) {
    asm volatile("ldmatrix.sync.aligned.m8n8.x2.trans.shared.b16 {%0,%1}, [%2];"
                 : "=r"(r[0]), "=r"(r[1]) : "r"(a));
}
__device__ __forceinline__ void mma_bf16(float* d, const uint32_t* a, const uint32_t* b) {
    asm volatile("mma.sync.aligned.m16n8k16.row.col.f32.bf16.bf16.f32 "
                 "{%0,%1,%2,%3}, {%4,%5,%6,%7}, {%8,%9}, {%0,%1,%2,%3};"
                 : "+f"(d[0]), "+f"(d[1]), "+f"(d[2]), "+f"(d[3])
                 : "r"(a[0]), "r"(a[1]), "r"(a[2]), "r"(a[3]), "r"(b[0]), "r"(b[1]));
}

// ---- fused weight transpose + split (all 6 weights, one launch) ----
struct WEnt { const float* W; __nv_bfloat16* hi; __nv_bfloat16* lo; int K; int N; int start; };
struct WTable { WEnt e[6]; int total; };

__global__ void wsplit_all(WTable t)
{
    __shared__ float tile[32][33];
    const int bid = blockIdx.x;
    const float* W = nullptr; __nv_bfloat16 *hi = nullptr, *lo = nullptr;
    int K = 0, N = 0, local = 0;
#pragma unroll
    for (int i = 0; i < 6; i++) {
        const int next = (i + 1 < 6) ? t.e[i + 1].start : t.total;
        if (bid >= t.e[i].start && bid < next) {
            W = t.e[i].W; hi = t.e[i].hi; lo = t.e[i].lo;
            K = t.e[i].K; N = t.e[i].N; local = bid - t.e[i].start;
        }
    }
    const int nb = N >> 5;
    const int n0 = (local % nb) * 32, k0 = (local / nb) * 32;
    const int tx = threadIdx.x, ty = threadIdx.y;
#pragma unroll
    for (int i = 0; i < 32; i += 8)
        tile[ty + i][tx] = W[(size_t)(k0 + ty + i) * N + n0 + tx];
    __syncthreads();
#pragma unroll
    for (int i = 0; i < 32; i += 8) {
        __nv_bfloat16 h_, l_;
        split2(tile[tx][ty + i], h_, l_);
        size_t o = (size_t)(n0 + ty + i) * K + k0 + tx;
        hi[o] = h_; lo[o] = l_;
    }
}

__global__ __launch_bounds__(256)
void xsplit_kernel(const float* __restrict__ x, __nv_bfloat16* __restrict__ hi,
                   __nv_bfloat16* __restrict__ lo, int n)
{
    int i = blockIdx.x * 256 + threadIdx.x;
    if (i < n) { __nv_bfloat16 h_, l_; split2(x[i], h_, l_); hi[i] = h_; lo[i] = l_; }
}

// ---- HMMA GEMM: split-3 bf16, CTA tile 128xBNx32, 4 warps ----
enum { EP_EMBED = 0, EP_BIAS = 1, EP_RES = 2, EP_GELU = 3, EP_SPLIT = 4 };

template <int EPI, int BN>
__global__ __launch_bounds__(128)
void hmma_gemm(int M, int N, int K,
               const __nv_bfloat16* __restrict__ Ahi, const __nv_bfloat16* __restrict__ Alo,
               const __nv_bfloat16* __restrict__ Bhi, const __nv_bfloat16* __restrict__ Blo,
               const float* __restrict__ bias, const float* __restrict__ extra,
               float* __restrict__ Cf,
               __nv_bfloat16* __restrict__ Chi, __nv_bfloat16* __restrict__ Clo)
{
    constexpr int NBJ = BN / 16;           // 8 for BN=128, 4 for BN=64 (warp tile N = BN/2)
    constexpr int BSTRIDE = BN * 64;       // bytes per B array per stage
    constexpr int STAGE = 16384 + 2 * BSTRIDE;

    extern __shared__ char dsm[];
    const uint32_t sbase = smem_u32(dsm);
    const int tid = threadIdx.x, wid = tid >> 5, lane = tid & 31;
    const int m0 = blockIdx.y * 128, n0 = blockIdx.x * BN;
    const int wm = (wid & 1) * 64, wn = (wid >> 1) * (BN / 2);

    float acc[4][NBJ][4];
#pragma unroll
    for (int i = 0; i < 4; i++)
#pragma unroll
        for (int j = 0; j < NBJ; j++)
#pragma unroll
            for (int q = 0; q < 4; q++) acc[i][j][q] = 0.f;

    uint32_t a_off[4], a_sw[4];
    const uint32_t a_half = lane >> 4;
#pragma unroll
    for (int i = 0; i < 4; i++) {
        int row = wm + i * 16 + (lane & 7) + ((lane >> 3) & 1) * 8;
        a_off[i] = row * 64;
        a_sw[i]  = (row >> 1) & 3;
    }
    uint32_t b_off[NBJ], b_sw[NBJ];
    const uint32_t b_half = (lane >> 3) & 1;
#pragma unroll
    for (int j = 0; j < NBJ; j++) {
        int row = wn + j * 8 + (lane & 7);
        b_off[j] = row * 64;
        b_sw[j]  = (row >> 1) & 3;
    }

    const int nch = K >> 5;
    auto stage = [&](int i) {
        const uint32_t buf = sbase + (i & 1) * STAGE;
        const int kofs = i << 5;
#pragma unroll
        for (int t = 0; t < 2; t++) {
            const __nv_bfloat16* src = t ? Alo : Ahi;
            const uint32_t db = buf + t * 8192;
#pragma unroll
            for (int u = 0; u < 4; u++) {
                int idx = u * 128 + tid;
                int row = idx >> 2, c = idx & 3;
                cpasync16(db + row * 64 + ((c ^ ((row >> 1) & 3)) << 4),
                          src + (size_t)(m0 + row) * K + kofs + c * 8);
            }
        }
#pragma unroll
        for (int t = 0; t < 2; t++) {
            const __nv_bfloat16* src = t ? Blo : Bhi;
            const uint32_t db = buf + 16384 + t * BSTRIDE;
#pragma unroll
            for (int u = 0; u < BN / 32; u++) {
                int idx = u * 128 + tid;
                int row = idx >> 2, c = idx & 3;
                cpasync16(db + row * 64 + ((c ^ ((row >> 1) & 3)) << 4),
                          src + (size_t)(n0 + row) * K + kofs + c * 8);
            }
        }
    };

    stage(0);
    asm volatile("cp.async.commit_group;" ::: "memory");

    for (int i = 0; i < nch; i++) {
        if (i + 1 < nch) {
            stage(i + 1);
            asm volatile("cp.async.commit_group;" ::: "memory");
            asm volatile("cp.async.wait_group 1;" ::: "memory");
        } else {
            asm volatile("cp.async.wait_group 0;" ::: "memory");
        }
        __syncthreads();

        const uint32_t buf = sbase + (i & 1) * STAGE;
#pragma unroll
        for (int p = 0; p < 3; p++) {
            const uint32_t ab = buf + (p == 1 ? 8192 : 0);
            const uint32_t bb = buf + 16384 + (p == 2 ? BSTRIDE : 0);
#pragma unroll
            for (int kk = 0; kk < 2; kk++) {
                uint32_t af[4][4], bf[NBJ][2];
#pragma unroll
                for (int t = 0; t < 4; t++)
                    ldm_x4(af[t], ab + a_off[t] + (((kk * 2 + a_half) ^ a_sw[t]) << 4));
#pragma unroll
                for (int j = 0; j < NBJ; j++)
                    ldm_x2(bf[j], bb + b_off[j] + (((kk * 2 + b_half) ^ b_sw[j]) << 4));
#pragma unroll
                for (int ti = 0; ti < 4; ti++)
#pragma unroll
                    for (int tj = 0; tj < NBJ; tj++)
                        mma_bf16(acc[ti][tj], af[ti], bf[tj]);
            }
        }
        __syncthreads();
    }

#pragma unroll
    for (int i = 0; i < 4; i++) {
#pragma unroll
        for (int half = 0; half < 2; half++) {
            const int row = m0 + wm + i * 16 + (lane >> 2) + half * 8;
#pragma unroll
            for (int j = 0; j < NBJ; j++) {
                const int col = n0 + wn + j * 8 + (lane & 3) * 2;
                float2 bv = *reinterpret_cast<const float2*>(bias + col);
                float v0 = acc[i][j][half * 2 + 0] + bv.x;
                float v1 = acc[i][j][half * 2 + 1] + bv.y;
                if (EPI == EP_EMBED || EPI == EP_RES) {
                    const int er = (EPI == EP_EMBED) ? (row & (LSEQ - 1)) : row;
                    float2 ev = *reinterpret_cast<const float2*>(extra + (size_t)er * N + col);
                    v0 += ev.x; v1 += ev.y;
                }
                if (EPI == EP_GELU) {
                    v0 = 0.5f * v0 * (1.f + erff(v0 * 0.70710678118654752f));
                    v1 = 0.5f * v1 * (1.f + erff(v1 * 0.70710678118654752f));
                }
                if (EPI == EP_GELU || EPI == EP_SPLIT) {
                    __nv_bfloat16 h0, l0, h1, l1;
                    split2(v0, h0, l0); split2(v1, h1, l1);
                    *reinterpret_cast<uint32_t*>(Chi + (size_t)row * N + col) = pack2(h0, h1);
                    *reinterpret_cast<uint32_t*>(Clo + (size_t)row * N + col) = pack2(l0, l1);
                } else {
                    *reinterpret_cast<float2*>(Cf + (size_t)row * N + col) = make_float2(v0, v1);
                }
            }
        }
    }
}

// ---- LayerNorm ----
template <bool WF32, bool WSPLIT>
__global__ __launch_bounds__(256)
void ln_kernel(const float* __restrict__ x, const float* __restrict__ w,
               const float* __restrict__ b, float* __restrict__ y,
               __nv_bfloat16* __restrict__ yhi, __nv_bfloat16* __restrict__ ylo)
{
    const int row = blockIdx.x, c = threadIdx.x * 4;
    float4 v = *reinterpret_cast<const float4*>(x + (size_t)row * DMODEL + c);
    float s = v.x + v.y + v.z + v.w;
    float sq = v.x*v.x + v.y*v.y + v.z*v.z + v.w*v.w;
#pragma unroll
    for (int o = 16; o; o >>= 1) {
        s += __shfl_xor_sync(~0u, s, o); sq += __shfl_xor_sync(~0u, sq, o);
    }
    __shared__ float ss[8], ssq[8];
    const int warp = threadIdx.x >> 5, lane = threadIdx.x & 31;
    if (lane == 0) { ss[warp] = s; ssq[warp] = sq; }
    __syncthreads();
    float tot = 0.f, totq = 0.f;
#pragma unroll
    for (int i = 0; i < 8; i++) { tot += ss[i]; totq += ssq[i]; }
    const float mu = tot / DMODEL, var = totq / DMODEL - mu * mu;
    const float inv = rsqrtf(var + LN_EPS);
    float4 wv = *reinterpret_cast<const float4*>(w + c);
    float4 bv = *reinterpret_cast<const float4*>(b + c);
    float4 o;
    o.x = (v.x-mu)*inv*wv.x + bv.x; o.y = (v.y-mu)*inv*wv.y + bv.y;
    o.z = (v.z-mu)*inv*wv.z + bv.z; o.w = (v.w-mu)*inv*wv.w + bv.w;
    if (WF32) *reinterpret_cast<float4*>(y + (size_t)row * DMODEL + c) = o;
    if (WSPLIT) {
        __nv_bfloat16 h0,l0,h1,l1,h2,l2,h3,l3;
        split2(o.x,h0,l0); split2(o.y,h1,l1); split2(o.z,h2,l2); split2(o.w,h3,l3);
        *reinterpret_cast<uint2*>(yhi + (size_t)row*DMODEL + c) = make_uint2(pack2(h0,h1), pack2(h2,h3));
        *reinterpret_cast<uint2*>(ylo + (size_t)row*DMODEL + c) = make_uint2(pack2(l0,l1), pack2(l2,l3));
    }
}

// ---- HMMA flash attention (causal), split-3 bf16, 8 warps x 16 q-rows ----
#define FA_SMEM (32768 + 2*32768)

__global__ __launch_bounds__(256, 1)
void fa_kernel(const __nv_bfloat16* __restrict__ kqhi, const __nv_bfloat16* __restrict__ kqlo,
               const __nv_bfloat16* __restrict__ vhi,  const __nv_bfloat16* __restrict__ vlo,
               __nv_bfloat16* __restrict__ ohi, __nv_bfloat16* __restrict__ olo)
{
    extern __shared__ char dsm[];
    const uint32_t sb = smem_u32(dsm);
    const int tid = threadIdx.x, w = tid >> 5, lane = tid & 31;
    const int qt = blockIdx.x, bh = blockIdx.y;
    const int bidx = bh >> 4, h = bh & 15;
    const int rowbase = bidx * LSEQ;
    const int q0 = qt * 128;
    const int jmax = 2 * qt + 1;

#pragma unroll
    for (int t = 0; t < 8; t++) {
        const int arr = t >> 2;
        const int row = ((t & 3) * 256 + tid) >> 3;
        const int ch = tid & 7;
        const __nv_bfloat16* base = arr ? kqlo : kqhi;
        cpasync16(sb + arr * 16384 + row * 128 + ((ch ^ (row & 7)) << 4),
                  base + (size_t)(rowbase + q0 + row) * (2 * DMODEL) + DMODEL + h * HD + ch * 8);
    }
    auto stageKV = [&](int jt, int b) {
        const uint32_t buf = sb + 32768 + b * 32768;
        const int n0 = jt * 64;
#pragma unroll
        for (int t = 0; t < 8; t++) {
            const int arr = t >> 1;
            const int row = ((t & 1) * 256 + tid) >> 3;
            const int ch = tid & 7;
            const __nv_bfloat16* base = (arr == 0) ? kqhi : (arr == 1) ? kqlo
                                      : (arr == 2) ? vhi : vlo;
            const size_t stride = (arr < 2) ? (2 * DMODEL) : DMODEL;
            cpasync16(buf + arr * 8192 + row * 128 + ((ch ^ (row & 7)) << 4),
                      base + (size_t)(rowbase + n0 + row) * stride + h * HD + ch * 8);
        }
    };
    stageKV(0, 0);
    asm volatile("cp.async.commit_group;" ::: "memory");

    const int r0 = q0 + w * 16 + (lane >> 2);
    float m0 = -INFINITY, m1 = -INFINITY, l0 = 0.f, l1 = 0.f;
    float o[8][4];
#pragma unroll
    for (int j = 0; j < 8; j++)
#pragma unroll
        for (int c = 0; c < 4; c++) o[j][c] = 0.f;

    uint32_t qh[4][4], ql[4][4];
    const int qrow = w * 16 + (lane & 7) + ((lane >> 3) & 1) * 8;
    const uint32_t qhalf = lane >> 4;

    for (int jt = 0; jt <= jmax; jt++) {
        if (jt < jmax) {
            stageKV(jt + 1, (jt + 1) & 1);
            asm volatile("cp.async.commit_group;" ::: "memory");
            asm volatile("cp.async.wait_group 1;" ::: "memory");
        } else {
            asm volatile("cp.async.wait_group 0;" ::: "memory");
        }
        __syncthreads();

        if (jt == 0) {
#pragma unroll
            for (int kc = 0; kc < 4; kc++) {
                const uint32_t co = (((kc * 2 + qhalf) ^ (qrow & 7)) << 4);
                ldm_x4(qh[kc], sb + qrow * 128 + co);
                ldm_x4(ql[kc], sb + 16384 + qrow * 128 + co);
            }
        }

        const uint32_t buf = sb + 32768 + (jt & 1) * 32768;
        const int n0 = jt * 64;

        float s[8][4];
#pragma unroll
        for (int j = 0; j < 8; j++) {
            s[j][0] = s[j][1] = s[j][2] = s[j][3] = 0.f;
            const int krow = j * 8 + (lane & 7);
            const uint32_t khalf = (lane >> 3) & 1;
#pragma unroll
            for (int kc = 0; kc < 4; kc++) {
                const uint32_t co = krow * 128 + (((kc * 2 + khalf) ^ (krow & 7)) << 4);
                uint32_t kh[2], kl[2];
                ldm_x2(kh, buf + co);
                ldm_x2(kl, buf + 8192 + co);
                mma_bf16(s[j], qh[kc], kh);
                mma_bf16(s[j], ql[kc], kh);
                mma_bf16(s[j], qh[kc], kl);
            }
        }
#pragma unroll
        for (int j = 0; j < 8; j++) {
            s[j][0] *= 0.125f; s[j][1] *= 0.125f; s[j][2] *= 0.125f; s[j][3] *= 0.125f;
        }
        if (n0 + 63 > q0 + w * 16) {
#pragma unroll
            for (int j = 0; j < 8; j++) {
                const int c0 = n0 + j * 8 + (lane & 3) * 2;
                if (c0 > r0)     s[j][0] = -INFINITY;
                if (c0 + 1 > r0) s[j][1] = -INFINITY;
                if (c0 > r0 + 8)     s[j][2] = -INFINITY;
                if (c0 + 1 > r0 + 8) s[j][3] = -INFINITY;
            }
        }
        float mx0 = -INFINITY, mx1 = -INFINITY;
#pragma unroll
        for (int j = 0; j < 8; j++) {
            mx0 = fmaxf(mx0, fmaxf(s[j][0], s[j][1]));
            mx1 = fmaxf(mx1, fmaxf(s[j][2], s[j][3]));
        }
        mx0 = fmaxf(mx0, __shfl_xor_sync(~0u, mx0, 1));
        mx0 = fmaxf(mx0, __shfl_xor_sync(~0u, mx0, 2));
        mx1 = fmaxf(mx1, __shfl_xor_sync(~0u, mx1, 1));
        mx1 = fmaxf(mx1, __shfl_xor_sync(~0u, mx1, 2));
        const float nm0 = fmaxf(m0, mx0), nm1 = fmaxf(m1, mx1);
        const float cr0 = __expf(m0 - nm0), cr1 = __expf(m1 - nm1);
        float rs0 = 0.f, rs1 = 0.f;
#pragma unroll
        for (int j = 0; j < 8; j++) {
            s[j][0] = __expf(s[j][0] - nm0); rs0 += s[j][0];
            s[j][1] = __expf(s[j][1] - nm0); rs0 += s[j][1];
            s[j][2] = __expf(s[j][2] - nm1); rs1 += s[j][2];
            s[j][3] = __expf(s[j][3] - nm1); rs1 += s[j][3];
        }
        rs0 += __shfl_xor_sync(~0u, rs0, 1); rs0 += __shfl_xor_sync(~0u, rs0, 2);
        rs1 += __shfl_xor_sync(~0u, rs1, 1); rs1 += __shfl_xor_sync(~0u, rs1, 2);
        l0 = l0 * cr0 + rs0; l1 = l1 * cr1 + rs1;
        m0 = nm0; m1 = nm1;
#pragma unroll
        for (int j = 0; j < 8; j++) {
            o[j][0] *= cr0; o[j][1] *= cr0; o[j][2] *= cr1; o[j][3] *= cr1;
        }
        uint32_t ph[4][4], pl[4][4];
#pragma unroll
        for (int kc = 0; kc < 4; kc++) {
#pragma unroll
            for (int half = 0; half < 2; half++) {
                const int t2 = 2 * kc + half;
                __nv_bfloat16 a0, b0, a1, b1;
                split2(s[t2][0], a0, b0); split2(s[t2][1], a1, b1);
                ph[kc][half * 2 + 0] = pack2(a0, a1);
                pl[kc][half * 2 + 0] = pack2(b0, b1);
                split2(s[t2][2], a0, b0); split2(s[t2][3], a1, b1);
                ph[kc][half * 2 + 1] = pack2(a0, a1);
                pl[kc][half * 2 + 1] = pack2(b0, b1);
            }
        }
#pragma unroll
        for (int j2 = 0; j2 < 8; j2++) {
#pragma unroll
            for (int kc = 0; kc < 4; kc++) {
                const int vrow = kc * 16 + (lane & 15);
                const uint32_t co = vrow * 128 + ((j2 ^ (vrow & 7)) << 4);
                uint32_t vh[2], vl[2];
                ldm_x2t(vh, buf + 16384 + co);
                ldm_x2t(vl, buf + 24576 + co);
                mma_bf16(o[j2], ph[kc], vh);
                mma_bf16(o[j2], pl[kc], vh);
                mma_bf16(o[j2], ph[kc], vl);
            }
        }
        __syncthreads();
    }

    const float il0 = 1.f / l0, il1 = 1.f / l1;
#pragma unroll
    for (int j2 = 0; j2 < 8; j2++) {
        const int col = h * HD + j2 * 8 + (lane & 3) * 2;
        float v0 = o[j2][0] * il0, v1 = o[j2][1] * il0;
        float v2 = o[j2][2] * il1, v3 = o[j2][3] * il1;
        __nv_bfloat16 h0, e0, h1, e1;
        split2(v0, h0, e0); split2(v1, h1, e1);
        *reinterpret_cast<uint32_t*>(ohi + (size_t)(rowbase + r0) * DMODEL + col) = pack2(h0, h1);
        *reinterpret_cast<uint32_t*>(olo + (size_t)(rowbase + r0) * DMODEL + col) = pack2(e0, e1);
        split2(v2, h0, e0); split2(v3, h1, e1);
        *reinterpret_cast<uint32_t*>(ohi + (size_t)(rowbase + r0 + 8) * DMODEL + col) = pack2(h0, h1);
        *reinterpret_cast<uint32_t*>(olo + (size_t)(rowbase + r0 + 8) * DMODEL + col) = pack2(e0, e1);
    }
}

extern "C" void kernel_launch(void* const* d_in, const int* in_sizes, int n_in,
                              void* d_out, int out_size)
{
    const float* x      = (const float*)d_in[0];
    const float* wte_w  = (const float*)d_in[1];
    const float* wte_b  = (const float*)d_in[2];
    const float* wpe    = (const float*)d_in[3];
    const float* ln1_w  = (const float*)d_in[4];
    const float* ln1_b  = (const float*)d_in[5];
    const float* kq_w   = (const float*)d_in[6];
    const float* kq_b   = (const float*)d_in[7];
    const float* v_w    = (const float*)d_in[8];
    const float* v_b    = (const float*)d_in[9];
    const float* ao_w   = (const float*)d_in[10];
    const float* ao_b   = (const float*)d_in[11];
    const float* ln2_w  = (const float*)d_in[12];
    const float* ln2_b  = (const float*)d_in[13];
    const float* fc_w   = (const float*)d_in[14];
    const float* fc_b   = (const float*)d_in[15];
    const float* proj_w = (const float*)d_in[16];
    const float* proj_b = (const float*)d_in[17];

    float *h, *hn;
    cudaGetSymbolAddress((void**)&h, g_h);
    cudaGetSymbolAddress((void**)&hn, g_hn);
    __nv_bfloat16 *xhi,*xlo,*hnhi,*hnlo,*kqhi,*kqlo,*vhi,*vlo,*ohi,*olo,*xohi,*xolo,*mlhi,*mllo;
    __nv_bfloat16 *wtehi,*wtelo,*kqwhi,*kqwlo,*vwhi,*vwlo,*aowhi,*aowlo,*fcwhi,*fcwlo,*pjwhi,*pjwlo;
    cudaGetSymbolAddress((void**)&xhi, g_x_hi);   cudaGetSymbolAddress((void**)&xlo, g_x_lo);
    cudaGetSymbolAddress((void**)&hnhi, g_hn_hi); cudaGetSymbolAddress((void**)&hnlo, g_hn_lo);
    cudaGetSymbolAddress((void**)&kqhi, g_kq_hi); cudaGetSymbolAddress((void**)&kqlo, g_kq_lo);
    cudaGetSymbolAddress((void**)&vhi, g_v_hi);   cudaGetSymbolAddress((void**)&vlo, g_v_lo);
    cudaGetSymbolAddress((void**)&ohi, g_o_hi);   cudaGetSymbolAddress((void**)&olo, g_o_lo);
    cudaGetSymbolAddress((void**)&xohi, g_xo_hi); cudaGetSymbolAddress((void**)&xolo, g_xo_lo);
    cudaGetSymbolAddress((void**)&mlhi, g_ml_hi); cudaGetSymbolAddress((void**)&mllo, g_ml_lo);
    cudaGetSymbolAddress((void**)&wtehi, g_wte_hi); cudaGetSymbolAddress((void**)&wtelo, g_wte_lo);
    cudaGetSymbolAddress((void**)&kqwhi, g_kqw_hi); cudaGetSymbolAddress((void**)&kqwlo, g_kqw_lo);
    cudaGetSymbolAddress((void**)&vwhi, g_vw_hi);   cudaGetSymbolAddress((void**)&vwlo, g_vw_lo);
    cudaGetSymbolAddress((void**)&aowhi, g_aow_hi); cudaGetSymbolAddress((void**)&aowlo, g_aow_lo);
    cudaGetSymbolAddress((void**)&fcwhi, g_fcw_hi); cudaGetSymbolAddress((void**)&fcwlo, g_fcw_lo);
    cudaGetSymbolAddress((void**)&pjwhi, g_pjw_hi); cudaGetSymbolAddress((void**)&pjwlo, g_pjw_lo);

    float* out0     = (float*)d_out;
    float* attn_out = out0 + (size_t)NTOK * INPUT_DIM;

    constexpr int SM128 = 2 * (16384 + 2 * 128 * 64);  // 65536
    constexpr int SM64  = 2 * (16384 + 2 * 64 * 64);   // 49152

    cudaFuncSetAttribute((const void*)hmma_gemm<EP_EMBED,128>, cudaFuncAttributeMaxDynamicSharedMemorySize, SM128);
    cudaFuncSetAttribute((const void*)hmma_gemm<EP_SPLIT,128>, cudaFuncAttributeMaxDynamicSharedMemorySize, SM128);
    cudaFuncSetAttribute((const void*)hmma_gemm<EP_RES,128>,   cudaFuncAttributeMaxDynamicSharedMemorySize, SM128);
    cudaFuncSetAttribute((const void*)hmma_gemm<EP_GELU,128>,  cudaFuncAttributeMaxDynamicSharedMemorySize, SM128);
    cudaFuncSetAttribute((const void*)hmma_gemm<EP_BIAS,64>,   cudaFuncAttributeMaxDynamicSharedMemorySize, SM64);
    cudaFuncSetAttribute((const void*)fa_kernel, cudaFuncAttributeMaxDynamicSharedMemorySize, FA_SMEM);

    // fused weight split table
    WTable wt;
    int cur = 0;
    auto set = [&](int i, const float* W, __nv_bfloat16* hi_, __nv_bfloat16* lo_, int K, int N) {
        wt.e[i].W = W; wt.e[i].hi = hi_; wt.e[i].lo = lo_;
        wt.e[i].K = K; wt.e[i].N = N; wt.e[i].start = cur;
        cur += (K / 32) * (N / 32);
    };
    set(0, wte_w,  wtehi, wtelo, INPUT_DIM, DMODEL);
    set(1, kq_w,   kqwhi, kqwlo, DMODEL, 2 * DMODEL);
    set(2, v_w,    vwhi,  vwlo,  DMODEL, DMODEL);
    set(3, ao_w,   aowhi, aowlo, DMODEL, DMODEL);
    set(4, fc_w,   fcwhi, fcwlo, DMODEL, MLPH);
    set(5, proj_w, pjwhi, pjwlo, MLPH, INPUT_DIM);
    wt.total = cur;

    dim3 wsb(32, 8);
    xsplit_kernel<<<(NTOK*INPUT_DIM)/256, 256>>>(x, xhi, xlo, NTOK*INPUT_DIM);
    wsplit_all<<<wt.total, wsb>>>(wt);

    hmma_gemm<EP_EMBED,128><<<dim3(DMODEL/128, NTOK/128), 128, SM128>>>(
        NTOK, DMODEL, INPUT_DIM, xhi, xlo, wtehi, wtelo, wte_b, wpe, h, nullptr, nullptr);
    ln_kernel<true, true><<<NTOK, 256>>>(h, ln1_w, ln1_b, hn, hnhi, hnlo);
    hmma_gemm<EP_SPLIT,128><<<dim3(2*DMODEL/128, NTOK/128), 128, SM128>>>(
        NTOK, 2*DMODEL, DMODEL, hnhi, hnlo, kqwhi, kqwlo, kq_b, nullptr, nullptr, kqhi, kqlo);
    hmma_gemm<EP_SPLIT,128><<<dim3(DMODEL/128, NTOK/128), 128, SM128>>>(
        NTOK, DMODEL, DMODEL, hnhi, hnlo, vwhi, vwlo, v_b, nullptr, nullptr, vhi, vlo);
    fa_kernel<<<dim3(LSEQ/128, BATCH*NHEAD), 256, FA_SMEM>>>(kqhi, kqlo, vhi, vlo, ohi, olo);
    hmma_gemm<EP_RES,128><<<dim3(DMODEL/128, NTOK/128), 128, SM128>>>(
        NTOK, DMODEL, DMODEL, ohi, olo, aowhi, aowlo, ao_b, hn, attn_out, nullptr, nullptr);
    ln_kernel<false, true><<<NTOK, 256>>>(attn_out, ln2_w, ln2_b, nullptr, xohi, xolo);
    hmma_gemm<EP_GELU,128><<<dim3(MLPH/128, NTOK/128), 128, SM128>>>(
        NTOK, MLPH, DMODEL, xohi, xolo, fcwhi, fcwlo, fc_b, nullptr, nullptr, mlhi, mllo);
    hmma_gemm<EP_BIAS,64><<<dim3(INPUT_DIM/64, NTOK/128), 128, SM64>>>(
        NTOK, INPUT_DIM, MLPH, mlhi, mllo, pjwhi, pjwlo, proj_b, nullptr, out0, nullptr, nullptr);
}

// round 15
// speedup vs baseline: 1.0535x; 1.0451x over previous
#include <cuda_runtime.h>
#include <cuda_bf16.h>
#include <math.h>
#include <stdint.h>

#define BATCH 2
#define LSEQ 2048
#define NTOK (BATCH*LSEQ)
#define INPUT_DIM 512
#define DMODEL 1024
#define NHEAD 16
#define HD 64
#define MLPH 4096
#define LN_EPS 1e-5f
// 0.125 * log2(e): folds softmax scale + exp->exp2 conversion
#define SCL2 0.18033688011112042f

// fp32 scratch
__device__ float g_h [NTOK*DMODEL];
__device__ float g_hn[NTOK*DMODEL];
// bf16 split activations
__device__ __nv_bfloat16 g_x_hi[NTOK*INPUT_DIM], g_x_lo[NTOK*INPUT_DIM];
__device__ __nv_bfloat16 g_hn_hi[NTOK*DMODEL],   g_hn_lo[NTOK*DMODEL];
__device__ __nv_bfloat16 g_kq_hi[NTOK*2*DMODEL], g_kq_lo[NTOK*2*DMODEL];
__device__ __nv_bfloat16 g_v_hi[NTOK*DMODEL],    g_v_lo[NTOK*DMODEL];
__device__ __nv_bfloat16 g_o_hi[NTOK*DMODEL],    g_o_lo[NTOK*DMODEL];
__device__ __nv_bfloat16 g_xo_hi[NTOK*DMODEL],   g_xo_lo[NTOK*DMODEL];
__device__ __nv_bfloat16 g_ml_hi[NTOK*MLPH],     g_ml_lo[NTOK*MLPH];
// bf16 split transposed weights [N][K]
__device__ __nv_bfloat16 g_wte_hi[DMODEL*INPUT_DIM], g_wte_lo[DMODEL*INPUT_DIM];
__device__ __nv_bfloat16 g_kqw_hi[2*DMODEL*DMODEL],  g_kqw_lo[2*DMODEL*DMODEL];
__device__ __nv_bfloat16 g_vw_hi[DMODEL*DMODEL],     g_vw_lo[DMODEL*DMODEL];
__device__ __nv_bfloat16 g_aow_hi[DMODEL*DMODEL],    g_aow_lo[DMODEL*DMODEL];
__device__ __nv_bfloat16 g_fcw_hi[MLPH*DMODEL],      g_fcw_lo[MLPH*DMODEL];
__device__ __nv_bfloat16 g_pjw_hi[INPUT_DIM*MLPH],   g_pjw_lo[INPUT_DIM*MLPH];

__device__ __forceinline__ void split2(float v, __nv_bfloat16& hi, __nv_bfloat16& lo) {
    hi = __float2bfloat16(v);
    lo = __float2bfloat16(v - __bfloat162float(hi));
}
__device__ __forceinline__ uint32_t pack2(__nv_bfloat16 a, __nv_bfloat16 b) {
    __nv_bfloat162 t = __halves2bfloat162(a, b);
    return *reinterpret_cast<uint32_t*>(&t);
}
__device__ __forceinline__ uint32_t smem_u32(const void* p) {
    return (uint32_t)__cvta_generic_to_shared(p);
}
__device__ __forceinline__ void cpasync16(uint32_t dst, const void* src) {
    asm volatile("cp.async.cg.shared.global [%0], [%1], 16;" :: "r"(dst), "l"(src));
}
__device__ __forceinline__ void ldm_x4(uint32_t* r, uint32_t a) {
    asm volatile("ldmatrix.sync.aligned.m8n8.x4.shared.b16 {%0,%1,%2,%3}, [%4];"
                 : "=r"(r[0]), "=r"(r[1]), "=r"(r[2]), "=r"(r[3]) : "r"(a));
}
__device__ __forceinline__ void ldm_x2(uint32_t* r, uint32_t a) {
    asm volatile("ldmatrix.sync.aligned.m8n8.x2.shared.b16 {%0,%1}, [%2];"
                 : "=r"(r[0]), "=r"(r[1]) : "r"(a));
}
__device__ __forceinline__ void ldm_x2t(uint32_t* r, uint32_t a) {
    asm volatile("ldmatrix.sync.aligned.m8n8.x2.trans.shared.b16 {%0,%1}, [%2];"
                 : "=r"(r[0]), "=r"(r[1]) : "r"(a));
}
__device__ __forceinline__ void mma_bf16(float* d, const uint32_t* a, const uint32_t* b) {
    asm volatile("mma.sync.aligned.m16n8k16.row.col.f32.bf16.bf16.f32 "
                 "{%0,%1,%2,%3}, {%4,%5,%6,%7}, {%8,%9}, {%0,%1,%2,%3};"
                 : "+f"(d[0]), "+f"(d[1]), "+f"(d[2]), "+f"(d[3])
                 : "r"(a[0]), "r"(a[1]), "r"(a[2]), "r"(a[3]), "r"(b[0]), "r"(b[1]));
}

// ---- fused weight transpose + split (all 6 weights, one launch) ----
struct WEnt { const float* W; __nv_bfloat16* hi; __nv_bfloat16* lo; int K; int N; int start; };
struct WTable { WEnt e[6]; int total; };

__global__ void wsplit_all(WTable t)
{
    __shared__ float tile[32][33];
    const int bid = blockIdx.x;
    const float* W = nullptr; __nv_bfloat16 *hi = nullptr, *lo = nullptr;
    int K = 0, N = 0, local = 0;
#pragma unroll
    for (int i = 0; i < 6; i++) {
        const int next = (i + 1 < 6) ? t.e[i + 1].start : t.total;
        if (bid >= t.e[i].start && bid < next) {
            W = t.e[i].W; hi = t.e[i].hi; lo = t.e[i].lo;
            K = t.e[i].K; N = t.e[i].N; local = bid - t.e[i].start;
        }
    }
    const int nb = N >> 5;
    const int n0 = (local % nb) * 32, k0 = (local / nb) * 32;
    const int tx = threadIdx.x, ty = threadIdx.y;
#pragma unroll
    for (int i = 0; i < 32; i += 8)
        tile[ty + i][tx] = W[(size_t)(k0 + ty + i) * N + n0 + tx];
    __syncthreads();
#pragma unroll
    for (int i = 0; i < 32; i += 8) {
        __nv_bfloat16 h_, l_;
        split2(tile[tx][ty + i], h_, l_);
        size_t o = (size_t)(n0 + ty + i) * K + k0 + tx;
        hi[o] = h_; lo[o] = l_;
    }
}

__global__ __launch_bounds__(256)
void xsplit_kernel(const float* __restrict__ x, __nv_bfloat16* __restrict__ hi,
                   __nv_bfloat16* __restrict__ lo, int n)
{
    int i = blockIdx.x * 256 + threadIdx.x;
    if (i < n) { __nv_bfloat16 h_, l_; split2(x[i], h_, l_); hi[i] = h_; lo[i] = l_; }
}

// ---- HMMA GEMM: split-3 bf16, CTA tile 128x128x32, 4 warps x (64x64) ----
enum { EP_EMBED = 0, EP_BIAS = 1, EP_RES = 2, EP_GELU = 3, EP_SPLIT = 4 };
#define HM_SMEM (2*32768)

template <int EPI>
__global__ __launch_bounds__(128)
void hmma_gemm(int M, int N, int K,
               const __nv_bfloat16* __restrict__ Ahi, const __nv_bfloat16* __restrict__ Alo,
               const __nv_bfloat16* __restrict__ Bhi, const __nv_bfloat16* __restrict__ Blo,
               const float* __restrict__ bias, const float* __restrict__ extra,
               float* __restrict__ Cf,
               __nv_bfloat16* __restrict__ Chi, __nv_bfloat16* __restrict__ Clo)
{
    extern __shared__ char dsm[];
    const uint32_t sbase = smem_u32(dsm);
    const int tid = threadIdx.x, wid = tid >> 5, lane = tid & 31;
    const int m0 = blockIdx.y * 128, n0 = blockIdx.x * 128;
    const int wm = (wid & 1) * 64, wn = (wid >> 1) * 64;

    float acc[4][8][4];
#pragma unroll
    for (int i = 0; i < 4; i++)
#pragma unroll
        for (int j = 0; j < 8; j++)
#pragma unroll
            for (int q = 0; q < 4; q++) acc[i][j][q] = 0.f;

    uint32_t a_off[4], a_sw[4];
    const uint32_t a_half = lane >> 4;
#pragma unroll
    for (int i = 0; i < 4; i++) {
        int row = wm + i * 16 + (lane & 7) + ((lane >> 3) & 1) * 8;
        a_off[i] = row * 64;
        a_sw[i]  = (row >> 1) & 3;
    }
    uint32_t b_off[8], b_sw[8];
    const uint32_t b_half = (lane >> 3) & 1;
#pragma unroll
    for (int j = 0; j < 8; j++) {
        int row = wn + j * 8 + (lane & 7);
        b_off[j] = row * 64;
        b_sw[j]  = (row >> 1) & 3;
    }

    const int nch = K >> 5;
    auto stage = [&](int i) {
        const uint32_t buf = sbase + (i & 1) * 32768;
        const int kofs = i << 5;
#pragma unroll
        for (int t = 0; t < 4; t++) {
            const __nv_bfloat16* src = (t == 0) ? Ahi : (t == 1) ? Alo : (t == 2) ? Bhi : Blo;
            const int rb = (t < 2) ? m0 : n0;
            const uint32_t db = buf + t * 8192;
#pragma unroll
            for (int u = 0; u < 4; u++) {
                int idx = u * 128 + tid;
                int row = idx >> 2, c = idx & 3;
                cpasync16(db + row * 64 + ((c ^ ((row >> 1) & 3)) << 4),
                          src + (size_t)(rb + row) * K + kofs + c * 8);
            }
        }
    };

    stage(0);
    asm volatile("cp.async.commit_group;" ::: "memory");

    for (int i = 0; i < nch; i++) {
        if (i + 1 < nch) {
            stage(i + 1);
            asm volatile("cp.async.commit_group;" ::: "memory");
            asm volatile("cp.async.wait_group 1;" ::: "memory");
        } else {
            asm volatile("cp.async.wait_group 0;" ::: "memory");
        }
        __syncthreads();

        const uint32_t buf = sbase + (i & 1) * 32768;
#pragma unroll
        for (int p = 0; p < 3; p++) {
            const uint32_t ab = buf + (p == 1 ? 8192 : 0);
            const uint32_t bb = buf + (p == 2 ? 24576 : 16384);
#pragma unroll
            for (int kk = 0; kk < 2; kk++) {
                uint32_t af[4][4], bf[8][2];
#pragma unroll
                for (int t = 0; t < 4; t++)
                    ldm_x4(af[t], ab + a_off[t] + (((kk * 2 + a_half) ^ a_sw[t]) << 4));
#pragma unroll
                for (int j = 0; j < 8; j++)
                    ldm_x2(bf[j], bb + b_off[j] + (((kk * 2 + b_half) ^ b_sw[j]) << 4));
#pragma unroll
                for (int ti = 0; ti < 4; ti++)
#pragma unroll
                    for (int tj = 0; tj < 8; tj++)
                        mma_bf16(acc[ti][tj], af[ti], bf[tj]);
            }
        }
        __syncthreads();
    }

#pragma unroll
    for (int i = 0; i < 4; i++) {
#pragma unroll
        for (int half = 0; half < 2; half++) {
            const int row = m0 + wm + i * 16 + (lane >> 2) + half * 8;
#pragma unroll
            for (int j = 0; j < 8; j++) {
                const int col = n0 + wn + j * 8 + (lane & 3) * 2;
                float2 bv = *reinterpret_cast<const float2*>(bias + col);
                float v0 = acc[i][j][half * 2 + 0] + bv.x;
                float v1 = acc[i][j][half * 2 + 1] + bv.y;
                if (EPI == EP_EMBED || EPI == EP_RES) {
                    const int er = (EPI == EP_EMBED) ? (row & (LSEQ - 1)) : row;
                    float2 ev = *reinterpret_cast<const float2*>(extra + (size_t)er * N + col);
                    v0 += ev.x; v1 += ev.y;
                }
                if (EPI == EP_GELU) {
                    v0 = 0.5f * v0 * (1.f + erff(v0 * 0.70710678118654752f));
                    v1 = 0.5f * v1 * (1.f + erff(v1 * 0.70710678118654752f));
                }
                if (EPI == EP_GELU || EPI == EP_SPLIT) {
                    __nv_bfloat16 h0, l0, h1, l1;
                    split2(v0, h0, l0); split2(v1, h1, l1);
                    *reinterpret_cast<uint32_t*>(Chi + (size_t)row * N + col) = pack2(h0, h1);
                    *reinterpret_cast<uint32_t*>(Clo + (size_t)row * N + col) = pack2(l0, l1);
                } else {
                    *reinterpret_cast<float2*>(Cf + (size_t)row * N + col) = make_float2(v0, v1);
                }
            }
        }
    }
}

// ---- LayerNorm ----
template <bool WF32, bool WSPLIT>
__global__ __launch_bounds__(256)
void ln_kernel(const float* __restrict__ x, const float* __restrict__ w,
               const float* __restrict__ b, float* __restrict__ y,
               __nv_bfloat16* __restrict__ yhi, __nv_bfloat16* __restrict__ ylo)
{
    const int row = blockIdx.x, c = threadIdx.x * 4;
    float4 v = *reinterpret_cast<const float4*>(x + (size_t)row * DMODEL + c);
    float s = v.x + v.y + v.z + v.w;
    float sq = v.x*v.x + v.y*v.y + v.z*v.z + v.w*v.w;
#pragma unroll
    for (int o = 16; o; o >>= 1) {
        s += __shfl_xor_sync(~0u, s, o); sq += __shfl_xor_sync(~0u, sq, o);
    }
    __shared__ float ss[8], ssq[8];
    const int warp = threadIdx.x >> 5, lane = threadIdx.x & 31;
    if (lane == 0) { ss[warp] = s; ssq[warp] = sq; }
    __syncthreads();
    float tot = 0.f, totq = 0.f;
#pragma unroll
    for (int i = 0; i < 8; i++) { tot += ss[i]; totq += ssq[i]; }
    const float mu = tot / DMODEL, var = totq / DMODEL - mu * mu;
    const float inv = rsqrtf(var + LN_EPS);
    float4 wv = *reinterpret_cast<const float4*>(w + c);
    float4 bv = *reinterpret_cast<const float4*>(b + c);
    float4 o;
    o.x = (v.x-mu)*inv*wv.x + bv.x; o.y = (v.y-mu)*inv*wv.y + bv.y;
    o.z = (v.z-mu)*inv*wv.z + bv.z; o.w = (v.w-mu)*inv*wv.w + bv.w;
    if (WF32) *reinterpret_cast<float4*>(y + (size_t)row * DMODEL + c) = o;
    if (WSPLIT) {
        __nv_bfloat16 h0,l0,h1,l1,h2,l2,h3,l3;
        split2(o.x,h0,l0); split2(o.y,h1,l1); split2(o.z,h2,l2); split2(o.w,h3,l3);
        *reinterpret_cast<uint2*>(yhi + (size_t)row*DMODEL + c) = make_uint2(pack2(h0,h1), pack2(h2,h3));
        *reinterpret_cast<uint2*>(ylo + (size_t)row*DMODEL + c) = make_uint2(pack2(l0,l1), pack2(l2,l3));
    }
}

// ---- HMMA flash attention (causal), split-3 bf16, 8 warps x 16 q-rows ----
// Softmax in log2 domain: scores scaled by 0.125*log2e, exp2f instead of __expf.
#define FA_SMEM (32768 + 2*32768)

__global__ __launch_bounds__(256, 1)
void fa_kernel(const __nv_bfloat16* __restrict__ kqhi, const __nv_bfloat16* __restrict__ kqlo,
               const __nv_bfloat16* __restrict__ vhi,  const __nv_bfloat16* __restrict__ vlo,
               __nv_bfloat16* __restrict__ ohi, __nv_bfloat16* __restrict__ olo)
{
    extern __shared__ char dsm[];
    const uint32_t sb = smem_u32(dsm);
    const int tid = threadIdx.x, w = tid >> 5, lane = tid & 31;
    const int qt = blockIdx.x, bh = blockIdx.y;
    const int bidx = bh >> 4, h = bh & 15;
    const int rowbase = bidx * LSEQ;
    const int q0 = qt * 128;
    const int jmax = 2 * qt + 1;

#pragma unroll
    for (int t = 0; t < 8; t++) {
        const int arr = t >> 2;
        const int row = ((t & 3) * 256 + tid) >> 3;
        const int ch = tid & 7;
        const __nv_bfloat16* base = arr ? kqlo : kqhi;
        cpasync16(sb + arr * 16384 + row * 128 + ((ch ^ (row & 7)) << 4),
                  base + (size_t)(rowbase + q0 + row) * (2 * DMODEL) + DMODEL + h * HD + ch * 8);
    }
    auto stageKV = [&](int jt, int b) {
        const uint32_t buf = sb + 32768 + b * 32768;
        const int n0 = jt * 64;
#pragma unroll
        for (int t = 0; t < 8; t++) {
            const int arr = t >> 1;
            const int row = ((t & 1) * 256 + tid) >> 3;
            const int ch = tid & 7;
            const __nv_bfloat16* base = (arr == 0) ? kqhi : (arr == 1) ? kqlo
                                      : (arr == 2) ? vhi : vlo;
            const size_t stride = (arr < 2) ? (2 * DMODEL) : DMODEL;
            cpasync16(buf + arr * 8192 + row * 128 + ((ch ^ (row & 7)) << 4),
                      base + (size_t)(rowbase + n0 + row) * stride + h * HD + ch * 8);
        }
    };
    stageKV(0, 0);
    asm volatile("cp.async.commit_group;" ::: "memory");

    const int r0 = q0 + w * 16 + (lane >> 2);
    float m0 = -INFINITY, m1 = -INFINITY, l0 = 0.f, l1 = 0.f;
    float o[8][4];
#pragma unroll
    for (int j = 0; j < 8; j++)
#pragma unroll
        for (int c = 0; c < 4; c++) o[j][c] = 0.f;

    uint32_t qh[4][4], ql[4][4];
    const int qrow = w * 16 + (lane & 7) + ((lane >> 3) & 1) * 8;
    const uint32_t qhalf = lane >> 4;

    for (int jt = 0; jt <= jmax; jt++) {
        if (jt < jmax) {
            stageKV(jt + 1, (jt + 1) & 1);
            asm volatile("cp.async.commit_group;" ::: "memory");
            asm volatile("cp.async.wait_group 1;" ::: "memory");
        } else {
            asm volatile("cp.async.wait_group 0;" ::: "memory");
        }
        __syncthreads();

        if (jt == 0) {
#pragma unroll
            for (int kc = 0; kc < 4; kc++) {
                const uint32_t co = (((kc * 2 + qhalf) ^ (qrow & 7)) << 4);
                ldm_x4(qh[kc], sb + qrow * 128 + co);
                ldm_x4(ql[kc], sb + 16384 + qrow * 128 + co);
            }
        }

        const uint32_t buf = sb + 32768 + (jt & 1) * 32768;
        const int n0 = jt * 64;

        float s[8][4];
#pragma unroll
        for (int j = 0; j < 8; j++) {
            s[j][0] = s[j][1] = s[j][2] = s[j][3] = 0.f;
            const int krow = j * 8 + (lane & 7);
            const uint32_t khalf = (lane >> 3) & 1;
#pragma unroll
            for (int kc = 0; kc < 4; kc++) {
                const uint32_t co = krow * 128 + (((kc * 2 + khalf) ^ (krow & 7)) << 4);
                uint32_t kh[2], kl[2];
                ldm_x2(kh, buf + co);
                ldm_x2(kl, buf + 8192 + co);
                mma_bf16(s[j], qh[kc], kh);
                mma_bf16(s[j], ql[kc], kh);
                mma_bf16(s[j], qh[kc], kl);
            }
        }
#pragma unroll
        for (int j = 0; j < 8; j++) {
            s[j][0] *= SCL2; s[j][1] *= SCL2; s[j][2] *= SCL2; s[j][3] *= SCL2;
        }
        if (n0 + 63 > q0 + w * 16) {
#pragma unroll
            for (int j = 0; j < 8; j++) {
                const int c0 = n0 + j * 8 + (lane & 3) * 2;
                if (c0 > r0)     s[j][0] = -INFINITY;
                if (c0 + 1 > r0) s[j][1] = -INFINITY;
                if (c0 > r0 + 8)     s[j][2] = -INFINITY;
                if (c0 + 1 > r0 + 8) s[j][3] = -INFINITY;
            }
        }
        float mx0 = -INFINITY, mx1 = -INFINITY;
#pragma unroll
        for (int j = 0; j < 8; j++) {
            mx0 = fmaxf(mx0, fmaxf(s[j][0], s[j][1]));
            mx1 = fmaxf(mx1, fmaxf(s[j][2], s[j][3]));
        }
        mx0 = fmaxf(mx0, __shfl_xor_sync(~0u, mx0, 1));
        mx0 = fmaxf(mx0, __shfl_xor_sync(~0u, mx0, 2));
        mx1 = fmaxf(mx1, __shfl_xor_sync(~0u, mx1, 1));
        mx1 = fmaxf(mx1, __shfl_xor_sync(~0u, mx1, 2));
        const float nm0 = fmaxf(m0, mx0), nm1 = fmaxf(m1, mx1);
        const float cr0 = exp2f(m0 - nm0), cr1 = exp2f(m1 - nm1);
        float rs0 = 0.f, rs1 = 0.f;
#pragma unroll
        for (int j = 0; j < 8; j++) {
            s[j][0] = exp2f(s[j][0] - nm0); rs0 += s[j][0];
            s[j][1] = exp2f(s[j][1] - nm0); rs0 += s[j][1];
            s[j][2] = exp2f(s[j][2] - nm1); rs1 += s[j][2];
            s[j][3] = exp2f(s[j][3] - nm1); rs1 += s[j][3];
        }
        rs0 += __shfl_xor_sync(~0u, rs0, 1); rs0 += __shfl_xor_sync(~0u, rs0, 2);
        rs1 += __shfl_xor_sync(~0u, rs1, 1); rs1 += __shfl_xor_sync(~0u, rs1, 2);
        l0 = l0 * cr0 + rs0; l1 = l1 * cr1 + rs1;
        m0 = nm0; m1 = nm1;
#pragma unroll
        for (int j = 0; j < 8; j++) {
            o[j][0] *= cr0; o[j][1] *= cr0; o[j][2] *= cr1; o[j][3] *= cr1;
        }
        uint32_t ph[4][4], pl[4][4];
#pragma unroll
        for (int kc = 0; kc < 4; kc++) {
#pragma unroll
            for (int half = 0; half < 2; half++) {
                const int t2 = 2 * kc + half;
                __nv_bfloat16 a0, b0, a1, b1;
                split2(s[t2][0], a0, b0); split2(s[t2][1], a1, b1);
                ph[kc][half * 2 + 0] = pack2(a0, a1);
                pl[kc][half * 2 + 0] = pack2(b0, b1);
                split2(s[t2][2], a0, b0); split2(s[t2][3], a1, b1);
                ph[kc][half * 2 + 1] = pack2(a0, a1);
                pl[kc][half * 2 + 1] = pack2(b0, b1);
            }
        }
#pragma unroll
        for (int j2 = 0; j2 < 8; j2++) {
#pragma unroll
            for (int kc = 0; kc < 4; kc++) {
                const int vrow = kc * 16 + (lane & 15);
                const uint32_t co = vrow * 128 + ((j2 ^ (vrow & 7)) << 4);
                uint32_t vh[2], vl[2];
                ldm_x2t(vh, buf + 16384 + co);
                ldm_x2t(vl, buf + 24576 + co);
                mma_bf16(o[j2], ph[kc], vh);
                mma_bf16(o[j2], pl[kc], vh);
                mma_bf16(o[j2], ph[kc], vl);
            }
        }
        __syncthreads();
    }

    const float il0 = 1.f / l0, il1 = 1.f / l1;
#pragma unroll
    for (int j2 = 0; j2 < 8; j2++) {
        const int col = h * HD + j2 * 8 + (lane & 3) * 2;
        float v0 = o[j2][0] * il0, v1 = o[j2][1] * il0;
        float v2 = o[j2][2] * il1, v3 = o[j2][3] * il1;
        __nv_bfloat16 h0, e0, h1, e1;
        split2(v0, h0, e0); split2(v1, h1, e1);
        *reinterpret_cast<uint32_t*>(ohi + (size_t)(rowbase + r0) * DMODEL + col) = pack2(h0, h1);
        *reinterpret_cast<uint32_t*>(olo + (size_t)(rowbase + r0) * DMODEL + col) = pack2(e0, e1);
        split2(v2, h0, e0); split2(v3, h1, e1);
        *reinterpret_cast<uint32_t*>(ohi + (size_t)(rowbase + r0 + 8) * DMODEL + col) = pack2(h0, h1);
        *reinterpret_cast<uint32_t*>(olo + (size_t)(rowbase + r0 + 8) * DMODEL + col) = pack2(e0, e1);
    }
}

extern "C" void kernel_launch(void* const* d_in, const int* in_sizes, int n_in,
                              void* d_out, int out_size)
{
    const float* x      = (const float*)d_in[0];
    const float* wte_w  = (const float*)d_in[1];
    const float* wte_b  = (const float*)d_in[2];
    const float* wpe    = (const float*)d_in[3];
    const float* ln1_w  = (const float*)d_in[4];
    const float* ln1_b  = (const float*)d_in[5];
    const float* kq_w   = (const float*)d_in[6];
    const float* kq_b   = (const float*)d_in[7];
    const float* v_w    = (const float*)d_in[8];
    const float* v_b    = (const float*)d_in[9];
    const float* ao_w   = (const float*)d_in[10];
    const float* ao_b   = (const float*)d_in[11];
    const float* ln2_w  = (const float*)d_in[12];
    const float* ln2_b  = (const float*)d_in[13];
    const float* fc_w   = (const float*)d_in[14];
    const float* fc_b   = (const float*)d_in[15];
    const float* proj_w = (const float*)d_in[16];
    const float* proj_b = (const float*)d_in[17];

    float *h, *hn;
    cudaGetSymbolAddress((void**)&h, g_h);
    cudaGetSymbolAddress((void**)&hn, g_hn);
    __nv_bfloat16 *xhi,*xlo,*hnhi,*hnlo,*kqhi,*kqlo,*vhi,*vlo,*ohi,*olo,*xohi,*xolo,*mlhi,*mllo;
    __nv_bfloat16 *wtehi,*wtelo,*kqwhi,*kqwlo,*vwhi,*vwlo,*aowhi,*aowlo,*fcwhi,*fcwlo,*pjwhi,*pjwlo;
    cudaGetSymbolAddress((void**)&xhi, g_x_hi);   cudaGetSymbolAddress((void**)&xlo, g_x_lo);
    cudaGetSymbolAddress((void**)&hnhi, g_hn_hi); cudaGetSymbolAddress((void**)&hnlo, g_hn_lo);
    cudaGetSymbolAddress((void**)&kqhi, g_kq_hi); cudaGetSymbolAddress((void**)&kqlo, g_kq_lo);
    cudaGetSymbolAddress((void**)&vhi, g_v_hi);   cudaGetSymbolAddress((void**)&vlo, g_v_lo);
    cudaGetSymbolAddress((void**)&ohi, g_o_hi);   cudaGetSymbolAddress((void**)&olo, g_o_lo);
    cudaGetSymbolAddress((void**)&xohi, g_xo_hi); cudaGetSymbolAddress((void**)&xolo, g_xo_lo);
    cudaGetSymbolAddress((void**)&mlhi, g_ml_hi); cudaGetSymbolAddress((void**)&mllo, g_ml_lo);
    cudaGetSymbolAddress((void**)&wtehi, g_wte_hi); cudaGetSymbolAddress((void**)&wtelo, g_wte_lo);
    cudaGetSymbolAddress((void**)&kqwhi, g_kqw_hi); cudaGetSymbolAddress((void**)&kqwlo, g_kqw_lo);
    cudaGetSymbolAddress((void**)&vwhi, g_vw_hi);   cudaGetSymbolAddress((void**)&vwlo, g_vw_lo);
    cudaGetSymbolAddress((void**)&aowhi, g_aow_hi); cudaGetSymbolAddress((void**)&aowlo, g_aow_lo);
    cudaGetSymbolAddress((void**)&fcwhi, g_fcw_hi); cudaGetSymbolAddress((void**)&fcwlo, g_fcw_lo);
    cudaGetSymbolAddress((void**)&pjwhi, g_pjw_hi); cudaGetSymbolAddress((void**)&pjwlo, g_pjw_lo);

    float* out0     = (float*)d_out;
    float* attn_out = out0 + (size_t)NTOK * INPUT_DIM;

    cudaFuncSetAttribute(hmma_gemm<EP_EMBED>, cudaFuncAttributeMaxDynamicSharedMemorySize, HM_SMEM);
    cudaFuncSetAttribute(hmma_gemm<EP_BIAS>,  cudaFuncAttributeMaxDynamicSharedMemorySize, HM_SMEM);
    cudaFuncSetAttribute(hmma_gemm<EP_RES>,   cudaFuncAttributeMaxDynamicSharedMemorySize, HM_SMEM);
    cudaFuncSetAttribute(hmma_gemm<EP_GELU>,  cudaFuncAttributeMaxDynamicSharedMemorySize, HM_SMEM);
    cudaFuncSetAttribute(hmma_gemm<EP_SPLIT>, cudaFuncAttributeMaxDynamicSharedMemorySize, HM_SMEM);
    cudaFuncSetAttribute(fa_kernel, cudaFuncAttributeMaxDynamicSharedMemorySize, FA_SMEM);

    // fused weight split table
    WTable wt;
    int cur = 0;
    auto set = [&](int i, const float* W, __nv_bfloat16* hi_, __nv_bfloat16* lo_, int K, int N) {
        wt.e[i].W = W; wt.e[i].hi = hi_; wt.e[i].lo = lo_;
        wt.e[i].K = K; wt.e[i].N = N; wt.e[i].start = cur;
        cur += (K / 32) * (N / 32);
    };
    set(0, wte_w,  wtehi, wtelo, INPUT_DIM, DMODEL);
    set(1, kq_w,   kqwhi, kqwlo, DMODEL, 2 * DMODEL);
    set(2, v_w,    vwhi,  vwlo,  DMODEL, DMODEL);
    set(3, ao_w,   aowhi, aowlo, DMODEL, DMODEL);
    set(4, fc_w,   fcwhi, fcwlo, DMODEL, MLPH);
    set(5, proj_w, pjwhi, pjwlo, MLPH, INPUT_DIM);
    wt.total = cur;

    dim3 wsb(32, 8);
    xsplit_kernel<<<(NTOK*INPUT_DIM)/256, 256>>>(x, xhi, xlo, NTOK*INPUT_DIM);
    wsplit_all<<<wt.total, wsb>>>(wt);

    hmma_gemm<EP_EMBED><<<dim3(DMODEL/128, NTOK/128), 128, HM_SMEM>>>(
        NTOK, DMODEL, INPUT_DIM, xhi, xlo, wtehi, wtelo, wte_b, wpe, h, nullptr, nullptr);
    ln_kernel<true, true><<<NTOK, 256>>>(h, ln1_w, ln1_b, hn, hnhi, hnlo);
    hmma_gemm<EP_SPLIT><<<dim3(2*DMODEL/128, NTOK/128), 128, HM_SMEM>>>(
        NTOK, 2*DMODEL, DMODEL, hnhi, hnlo, kqwhi, kqwlo, kq_b, nullptr, nullptr, kqhi, kqlo);
    hmma_gemm<EP_SPLIT><<<dim3(DMODEL/128, NTOK/128), 128, HM_SMEM>>>(
        NTOK, DMODEL, DMODEL, hnhi, hnlo, vwhi, vwlo, v_b, nullptr, nullptr, vhi, vlo);
    fa_kernel<<<dim3(LSEQ/128, BATCH*NHEAD), 256, FA_SMEM>>>(kqhi, kqlo, vhi, vlo, ohi, olo);
    hmma_gemm<EP_RES><<<dim3(DMODEL/128, NTOK/128), 128, HM_SMEM>>>(
        NTOK, DMODEL, DMODEL, ohi, olo, aowhi, aowlo, ao_b, hn, attn_out, nullptr, nullptr);
    ln_kernel<false, true><<<NTOK, 256>>>(attn_out, ln2_w, ln2_b, nullptr, xohi, xolo);
    hmma_gemm<EP_GELU><<<dim3(MLPH/128, NTOK/128), 128, HM_SMEM>>>(
        NTOK, MLPH, DMODEL, xohi, xolo, fcwhi, fcwlo, fc_b, nullptr, nullptr, mlhi, mllo);
    hmma_gemm<EP_BIAS><<<dim3(INPUT_DIM/128, NTOK/128), 128, HM_SMEM>>>(
        NTOK, INPUT_DIM, MLPH, mlhi, mllo, pjwhi, pjwlo, proj_b, nullptr, out0, nullptr, nullptr);
}